// round 8
// baseline (speedup 1.0000x reference)
#include <cuda_runtime.h>
#include <cstdint>
#include <cstddef>

#define B       256
#define NIN     1152
#define NOUT    10
#define DOUT    16
#define DIN     8
#define OJ      160        // NOUT*DOUT
#define BT      32         // batch tile per CTA
#define NCH     48         // n-chunks (grid 48x8 = 384 CTAs -> 2.6/SM, 1 wave @ occ3)
#define NPER    24         // NIN / NCH
#define NT      160        // pass kernel threads (5 warps)

typedef unsigned long long u64;

// ------------------------------------------------------------------
// scratch (no allocations allowed -> __device__ globals)
// ------------------------------------------------------------------
__device__ float g_partial[NCH][B][OJ];   // per-chunk partial s (7.9 MB)
__device__ float g_vsum[B][OJ];           // cumulative v over rounds

// ------------------------------------------------------------------
// packed f32x2 helpers (sm_100+)
// ------------------------------------------------------------------
__device__ __forceinline__ u64 fma2(u64 a, u64 b, u64 c) {
    u64 d; asm("fma.rn.f32x2 %0,%1,%2,%3;" : "=l"(d) : "l"(a), "l"(b), "l"(c)); return d;
}
__device__ __forceinline__ u64 mul2(u64 a, u64 b) {
    u64 d; asm("mul.rn.f32x2 %0,%1,%2;" : "=l"(d) : "l"(a), "l"(b)); return d;
}
__device__ __forceinline__ u64 add2(u64 a, u64 b) {
    u64 d; asm("add.rn.f32x2 %0,%1,%2;" : "=l"(d) : "l"(a), "l"(b)); return d;
}
__device__ __forceinline__ u64 pk2(float lo, float hi) {
    u64 d; asm("mov.b64 %0,{%1,%2};" : "=l"(d) : "f"(lo), "f"(hi)); return d;
}
__device__ __forceinline__ void upk2(u64 v, float& lo, float& hi) {
    asm("mov.b64 {%0,%1},%2;" : "=f"(lo), "=f"(hi) : "l"(v));
}

// ------------------------------------------------------------------
// Pass kernel (one routing round), 160 threads:
//   t = h*80 + q*16 + j   (h: batch half, q in [0,5), j in [0,16))
//   thread owns oj slots p0 = 32q + j (o=2q) and p1 = p0+16 (o=2q+1),
//   and 16 batch elements (8 f32x2 pairs) [b0+16h, b0+16h+16).
// Per iter: 128 fma2 fed by 32 LDS.128 (x) + 16 LDS.64 (W) -> 4:1 reuse.
// W[n+1]/x[n+1] prefetched via LDG at iter top, staged into the
// alternate SMEM buffer late in the iteration.
// ------------------------------------------------------------------
template<int ROUND>
__global__ void __launch_bounds__(NT, 3)
pass_kernel(const float* __restrict__ x, const float* __restrict__ W)
{
    const int nc = blockIdx.x;
    const int b0 = blockIdx.y * BT;
    const int t  = threadIdx.x;
    const int j  = t & 15;
    const int q  = (t >> 4) % 5;
    const int h  = t / 80;
    const int p0 = q * 32 + j;          // o = 2q
    const int p1 = p0 + 16;             // o = 2q+1
    const int o0 = 2 * q;
    const int o1 = 2 * q + 1;

    // W staging mapping: thread loads float4 at [n*320 + t] and [n*320 + t + 160]
    const int wiA = (t >> 2) & 7;
    const int wcA = (t >> 5) * 16 + (t & 3) * 4;   // oA*16 + jA
    // x staging (t<64): b = t/2, half = t&1
    const int xb = t >> 1;
    const int xh = t & 1;

    __shared__ __align__(16) u64   W2s[2][DIN][OJ + 2]; // [buf][i][oj]={w,w} 20.25KB
    __shared__ __align__(16) float x2f[2][DIN][BT];     // [buf][i][b]         2KB
    __shared__ __align__(16) float p_s[OJ][BT + 2];     // agreement partials 21.25KB
    __shared__ __align__(16) float e_s[NOUT][BT];       // exp(agreement)
    __shared__ __align__(16) float r_s[BT];             // 1/sum_o exp

    const float4* __restrict__ Wg = reinterpret_cast<const float4*>(W);
    const float4* __restrict__ xrow =
        reinterpret_cast<const float4*>(x + (size_t)(b0 + xb) * NIN * DIN);

    u64 s2a[8], s2b[8];
    #pragma unroll
    for (int k = 0; k < 8; ++k) { s2a[k] = 0ULL; s2b[k] = 0ULL; }

    u64 vs2a[8], vs2b[8];
    if (ROUND > 0) {
        #pragma unroll
        for (int k = 0; k < 8; ++k) {
            const int b = b0 + 2 * (h * 8 + k);
            vs2a[k] = pk2(g_vsum[b][p0], g_vsum[b + 1][p0]);
            vs2b[k] = pk2(g_vsum[b][p1], g_vsum[b + 1][p1]);
        }
    }

    const int nbase = nc * NPER;

    // ---- prologue: load + stage n=0 into buffer 0 ----
    float4 w4a = Wg[(size_t)nbase * 320 + t];
    float4 w4b = Wg[(size_t)nbase * 320 + t + 160];
    float4 xv;
    if (t < 64) xv = xrow[(size_t)nbase * 2 + xh];
    {
        ulonglong2* wpA = reinterpret_cast<ulonglong2*>(&W2s[0][wiA][wcA]);
        ulonglong2* wpB = reinterpret_cast<ulonglong2*>(&W2s[0][wiA][wcA + 80]);
        wpA[0] = make_ulonglong2(pk2(w4a.x, w4a.x), pk2(w4a.y, w4a.y));
        wpA[1] = make_ulonglong2(pk2(w4a.z, w4a.z), pk2(w4a.w, w4a.w));
        wpB[0] = make_ulonglong2(pk2(w4b.x, w4b.x), pk2(w4b.y, w4b.y));
        wpB[1] = make_ulonglong2(pk2(w4b.z, w4b.z), pk2(w4b.w, w4b.w));
        if (t < 64) {
            x2f[0][xh * 4 + 0][xb] = xv.x;
            x2f[0][xh * 4 + 1][xb] = xv.y;
            x2f[0][xh * 4 + 2][xb] = xv.z;
            x2f[0][xh * 4 + 3][xb] = xv.w;
        }
    }
    __syncthreads();

    for (int nn = 0; nn < NPER; ++nn) {
        const int buf  = nn & 1;
        const int nbuf = buf ^ 1;

        // ---- prefetch n+1 (clamped) into registers ----
        const int n1 = nbase + ((nn + 1 < NPER) ? nn + 1 : nn);
        w4a = Wg[(size_t)n1 * 320 + t];
        w4b = Wg[(size_t)n1 * 320 + t + 160];
        if (t < 64) xv = xrow[(size_t)n1 * 2 + xh];

        // ---- u_hat for p0,p1 over 8 batch pairs ----
        u64 u2a[8], u2b[8];
        #pragma unroll
        for (int k = 0; k < 8; ++k) { u2a[k] = 0ULL; u2b[k] = 0ULL; }
        #pragma unroll
        for (int i = 0; i < 8; ++i) {
            const u64 w0 = W2s[buf][i][p0];
            const u64 w1 = W2s[buf][i][p1];
            const ulonglong2* xp =
                reinterpret_cast<const ulonglong2*>(&x2f[buf][i][h * 16]);
            #pragma unroll
            for (int qq = 0; qq < 4; ++qq) {
                ulonglong2 xq = xp[qq];
                u2a[2 * qq]     = fma2(w0, xq.x, u2a[2 * qq]);
                u2a[2 * qq + 1] = fma2(w0, xq.y, u2a[2 * qq + 1]);
                u2b[2 * qq]     = fma2(w1, xq.x, u2b[2 * qq]);
                u2b[2 * qq + 1] = fma2(w1, xq.y, u2b[2 * qq + 1]);
            }
        }

        if (ROUND == 0) {
            #pragma unroll
            for (int k = 0; k < 8; ++k) {
                s2a[k] = add2(s2a[k], u2a[k]);
                s2b[k] = add2(s2b[k], u2b[k]);
            }
            // stage n+1
            ulonglong2* wpA = reinterpret_cast<ulonglong2*>(&W2s[nbuf][wiA][wcA]);
            ulonglong2* wpB = reinterpret_cast<ulonglong2*>(&W2s[nbuf][wiA][wcA + 80]);
            wpA[0] = make_ulonglong2(pk2(w4a.x, w4a.x), pk2(w4a.y, w4a.y));
            wpA[1] = make_ulonglong2(pk2(w4a.z, w4a.z), pk2(w4a.w, w4a.w));
            wpB[0] = make_ulonglong2(pk2(w4b.x, w4b.x), pk2(w4b.y, w4b.y));
            wpB[1] = make_ulonglong2(pk2(w4b.z, w4b.z), pk2(w4b.w, w4b.w));
            if (t < 64) {
                x2f[nbuf][xh * 4 + 0][xb] = xv.x;
                x2f[nbuf][xh * 4 + 1][xb] = xv.y;
                x2f[nbuf][xh * 4 + 2][xb] = xv.z;
                x2f[nbuf][xh * 4 + 3][xb] = xv.w;
            }
            __syncthreads();
        } else {
            // ---- agreement partial products -> p_s ----
            #pragma unroll
            for (int k = 0; k < 8; ++k) {
                const int bp2 = 2 * (h * 8 + k);
                *reinterpret_cast<u64*>(&p_s[p0][bp2]) = mul2(u2a[k], vs2a[k]);
                *reinterpret_cast<u64*>(&p_s[p1][bp2]) = mul2(u2b[k], vs2b[k]);
            }
            __syncthreads();

            // ---- reduce over j + exp: thread -> o = t>>5 and (t>>5)+5, rb = t&31 ----
            {
                const int ro = t >> 5;
                const int rb = t & 31;
                float a0 = 0.f, a1 = 0.f;
                #pragma unroll
                for (int jj = 0; jj < 16; ++jj) {
                    a0 += p_s[ro * 16 + jj][rb];
                    a1 += p_s[(ro + 5) * 16 + jj][rb];
                }
                e_s[ro][rb]     = __expf(a0);  // |a| tiny -> matches max-shifted softmax
                e_s[ro + 5][rb] = __expf(a1);
            }
            __syncthreads();

            // ---- r_s by warp 0; everyone stages n+1 under it ----
            if (t < BT) {
                float ssum = 0.f;
                #pragma unroll
                for (int oo = 0; oo < NOUT; ++oo) ssum += e_s[oo][t];
                r_s[t] = 1.0f / ssum;
            }
            {
                ulonglong2* wpA = reinterpret_cast<ulonglong2*>(&W2s[nbuf][wiA][wcA]);
                ulonglong2* wpB = reinterpret_cast<ulonglong2*>(&W2s[nbuf][wiA][wcA + 80]);
                wpA[0] = make_ulonglong2(pk2(w4a.x, w4a.x), pk2(w4a.y, w4a.y));
                wpA[1] = make_ulonglong2(pk2(w4a.z, w4a.z), pk2(w4a.w, w4a.w));
                wpB[0] = make_ulonglong2(pk2(w4b.x, w4b.x), pk2(w4b.y, w4b.y));
                wpB[1] = make_ulonglong2(pk2(w4b.z, w4b.z), pk2(w4b.w, w4b.w));
                if (t < 64) {
                    x2f[nbuf][xh * 4 + 0][xb] = xv.x;
                    x2f[nbuf][xh * 4 + 1][xb] = xv.y;
                    x2f[nbuf][xh * 4 + 2][xb] = xv.z;
                    x2f[nbuf][xh * 4 + 3][xb] = xv.w;
                }
            }
            __syncthreads();

            // ---- reweight: s += c * u_hat ----
            #pragma unroll
            for (int k = 0; k < 8; ++k) {
                const int bp2 = 2 * (h * 8 + k);
                u64 rv = *reinterpret_cast<const u64*>(&r_s[bp2]);
                u64 e0 = *reinterpret_cast<const u64*>(&e_s[o0][bp2]);
                u64 e1 = *reinterpret_cast<const u64*>(&e_s[o1][bp2]);
                s2a[k] = fma2(mul2(e0, rv), u2a[k], s2a[k]);
                s2b[k] = fma2(mul2(e1, rv), u2b[k], s2b[k]);
            }
            // no trailing barrier: all shared reads here are separated from the
            // next writers (p_s/e_s/r_s/W2s[nbuf]) by >=1 barrier next iteration.
        }
    }

    // ---- write per-chunk partial (deterministic, no atomics) ----
    const float scale = (ROUND == 0) ? 0.1f : 1.0f;
    #pragma unroll
    for (int k = 0; k < 8; ++k) {
        const int b = b0 + 2 * (h * 8 + k);
        float lo, hi;
        upk2(s2a[k], lo, hi);
        g_partial[nc][b][p0]     = lo * scale;
        g_partial[nc][b + 1][p0] = hi * scale;
        upk2(s2b[k], lo, hi);
        g_partial[nc][b][p1]     = lo * scale;
        g_partial[nc][b + 1][p1] = hi * scale;
    }
}

// ------------------------------------------------------------------
// Squash: one (b,oj) output per thread, 48 fully-independent LDGs
// (MLP=48), 16-lane shfl for the j-norm. 160 blocks x 256 threads.
// ------------------------------------------------------------------
template<int ROUND>
__global__ void __launch_bounds__(256)
squash_kernel(float* __restrict__ out)
{
    const int g = blockIdx.x * 256 + threadIdx.x;   // [0, 40960)
    const float* gp = &g_partial[0][0][0];

    float s = 0.f;
    #pragma unroll
    for (int c = 0; c < NCH; ++c) s += gp[(size_t)c * (B * OJ) + g];

    // 16-lane groups share (b,o); j = low 4 bits of lane (16 | 160, 16 | 256)
    float nsq = s * s;
    #pragma unroll
    for (int m = 1; m < 16; m <<= 1)
        nsq += __shfl_xor_sync(0xffffffffu, nsq, m);

    const float norm = sqrtf(nsq + 1e-9f);
    const float v = s * (nsq / ((1.0f + nsq) * norm));

    float* vs = &g_vsum[0][0];
    if (ROUND == 0)       vs[g] = v;
    else if (ROUND == 1)  vs[g] += v;
    else                  out[g] = v;
}

// ------------------------------------------------------------------
// no-op launch: keeps the ncu -s/-c capture window on pass_kernel<1>
// ------------------------------------------------------------------
__global__ void noop_kernel() {}

// ------------------------------------------------------------------
extern "C" void kernel_launch(void* const* d_in, const int* in_sizes, int n_in,
                              void* d_out, int out_size)
{
    const float* a0 = (const float*)d_in[0];
    const float* a1 = (const float*)d_in[1];
    const float* x;
    const float* W;
    if (in_sizes[0] == B * NIN * DIN) { x = a0; W = a1; }
    else                              { x = a1; W = a0; }
    float* out = (float*)d_out;

    dim3 pg(NCH, B / BT);   // 48 x 8 = 384 CTAs

    noop_kernel<<<1, 32>>>();
    pass_kernel<0><<<pg, NT>>>(x, W);
    squash_kernel<0><<<160, 256>>>(out);
    pass_kernel<1><<<pg, NT>>>(x, W);
    squash_kernel<1><<<160, 256>>>(out);
    pass_kernel<2><<<pg, NT>>>(x, W);
    squash_kernel<2><<<160, 256>>>(out);
}

// round 9
// speedup vs baseline: 1.1515x; 1.1515x over previous
#include <cuda_runtime.h>
#include <cstdint>
#include <cstddef>

#define B       256
#define NIN     1152
#define NOUT    10
#define DOUT    16
#define DIN     8
#define OJ      160        // NOUT*DOUT
#define BT      32         // batch tile per CTA (16 pairs)
#define NBP     16         // batch pairs per CTA
#define NCH     48         // n-chunks (grid 48x8 = 384 CTAs)
#define NPER    24         // NIN / NCH
#define NT      160        // pass kernel threads (5 warps)

typedef unsigned long long u64;

// ------------------------------------------------------------------
// scratch (pair-major: element [bp][p] = {val[2bp][p], val[2bp+1][p]})
// ------------------------------------------------------------------
__device__ u64 g_partial2[NCH][B / 2][OJ];   // per-chunk partial s (7.9 MB)
__device__ u64 g_vsum2[B / 2][OJ];           // cumulative v over rounds

// ------------------------------------------------------------------
// packed f32x2 helpers (sm_100+)
// ------------------------------------------------------------------
__device__ __forceinline__ u64 fma2(u64 a, u64 b, u64 c) {
    u64 d; asm("fma.rn.f32x2 %0,%1,%2,%3;" : "=l"(d) : "l"(a), "l"(b), "l"(c)); return d;
}
__device__ __forceinline__ u64 mul2(u64 a, u64 b) {
    u64 d; asm("mul.rn.f32x2 %0,%1,%2;" : "=l"(d) : "l"(a), "l"(b)); return d;
}
__device__ __forceinline__ u64 add2(u64 a, u64 b) {
    u64 d; asm("add.rn.f32x2 %0,%1,%2;" : "=l"(d) : "l"(a), "l"(b)); return d;
}
__device__ __forceinline__ u64 pk2(float lo, float hi) {
    u64 d; asm("mov.b64 %0,{%1,%2};" : "=l"(d) : "f"(lo), "f"(hi)); return d;
}
__device__ __forceinline__ void upk2(u64 v, float& lo, float& hi) {
    asm("mov.b64 {%0,%1},%2;" : "=f"(lo), "=f"(hi) : "l"(v));
}
__device__ __forceinline__ u64 shfl_xor64(u64 v, int m) {
    uint32_t lo = (uint32_t)v, hi = (uint32_t)(v >> 32);
    lo = __shfl_xor_sync(0xffffffffu, lo, m);
    hi = __shfl_xor_sync(0xffffffffu, hi, m);
    return ((u64)hi << 32) | lo;
}

// ------------------------------------------------------------------
// Pass kernel (one routing round), 160 threads:
//   t = h*40 + u,  h in [0,4): batch pairs 4h..4h+3 (8 batches)
//   u in [0,40): o = u>>2, jq = u&3 -> thread owns oj slots
//   p = 4u + c (c=0..3), ALL with the same o.
// x is warp-broadcast (all lanes of an h-group read the same 32B/i);
// W read un-duplicated as one LDS.128 per i, packed to f32x2 in regs.
// Agreement j-reduction: 3 in-reg fma2 + 4-lane shfl butterfly
// (lanes u=4o+jq, groups 4-aligned in lane space since 40h%4==0).
// ------------------------------------------------------------------
template<int ROUND>
__global__ void __launch_bounds__(NT, 3)
pass_kernel(const float* __restrict__ x, const float* __restrict__ W)
{
    const int nc  = blockIdx.x;
    const int b0  = blockIdx.y * BT;
    const int bp0 = blockIdx.y * NBP;
    const int t   = threadIdx.x;
    const int h   = t / 40;
    const int u   = t % 40;
    const int o   = u >> 2;
    const int jq  = u & 3;
    const int pb  = 4 * u;              // p_base = o*16 + 4*jq

    // W staging: thread t stores float4s (flat 4t and 4t+640) to
    //   W1s[i_s][o_s*16 + j_s] and [...][+80]
    const int wiA = (t >> 2) & 7;
    const int wcA = (t >> 5) * 16 + (t & 3) * 4;
    // x staging (t<64): b = t/2, half = t&1
    const int xb = t >> 1;
    const int xh = t & 1;

    __shared__ __align__(16) float W1s[2][DIN][OJ + 4];  // un-dup W   10.5KB
    __shared__ __align__(16) float x2f[2][DIN][BT];      // [i][b]      2KB
    __shared__ __align__(16) u64   vs_s[NBP][OJ];        // vsum slice 20.5KB
    __shared__ __align__(16) float e_s[2][NOUT][BT];     // exp(agr)   2.5KB
    __shared__ __align__(16) float r_s[2][BT];           // 1/sum_o

    const float4* __restrict__ Wg = reinterpret_cast<const float4*>(W);
    const float4* __restrict__ xrow =
        reinterpret_cast<const float4*>(x + (size_t)(b0 + xb) * NIN * DIN);

    // ---- load this CTA's vsum slice into smem (coalesced) ----
    if (ROUND > 0) {
        const ulonglong2* src =
            reinterpret_cast<const ulonglong2*>(&g_vsum2[bp0][0]);
        ulonglong2* dst = reinterpret_cast<ulonglong2*>(&vs_s[0][0]);
        #pragma unroll
        for (int r = 0; r < 8; ++r) dst[r * NT + t] = src[r * NT + t];
    }

    u64 s2[4][4];                        // [c][k] accumulators
    #pragma unroll
    for (int c = 0; c < 4; ++c)
        #pragma unroll
        for (int k = 0; k < 4; ++k) s2[c][k] = 0ULL;

    const int nbase = nc * NPER;

    // ---- prologue: load + stage n=0 into buffer 0 ----
    float4 w4a = Wg[(size_t)nbase * 320 + t];
    float4 w4b = Wg[(size_t)nbase * 320 + t + 160];
    float4 xv;
    if (t < 64) xv = xrow[(size_t)nbase * 2 + xh];
    *reinterpret_cast<float4*>(&W1s[0][wiA][wcA])      = w4a;
    *reinterpret_cast<float4*>(&W1s[0][wiA][wcA + 80]) = w4b;
    if (t < 64) {
        x2f[0][xh * 4 + 0][xb] = xv.x;
        x2f[0][xh * 4 + 1][xb] = xv.y;
        x2f[0][xh * 4 + 2][xb] = xv.z;
        x2f[0][xh * 4 + 3][xb] = xv.w;
    }
    __syncthreads();

    for (int nn = 0; nn < NPER; ++nn) {
        const int buf  = nn & 1;
        const int nbuf = buf ^ 1;

        // ---- prefetch n+1 (clamped) ----
        const int n1 = nbase + ((nn + 1 < NPER) ? nn + 1 : nn);
        w4a = Wg[(size_t)n1 * 320 + t];
        w4b = Wg[(size_t)n1 * 320 + t + 160];
        if (t < 64) xv = xrow[(size_t)n1 * 2 + xh];

        // ---- u_hat: 4 oj x 4 bp, x broadcast, W packed in regs ----
        u64 u2[4][4];
        #pragma unroll
        for (int c = 0; c < 4; ++c)
            #pragma unroll
            for (int k = 0; k < 4; ++k) u2[c][k] = 0ULL;
        #pragma unroll
        for (int i = 0; i < DIN; ++i) {
            const float4 wq = *reinterpret_cast<const float4*>(&W1s[buf][i][pb]);
            const u64 wc0 = pk2(wq.x, wq.x);
            const u64 wc1 = pk2(wq.y, wq.y);
            const u64 wc2 = pk2(wq.z, wq.z);
            const u64 wc3 = pk2(wq.w, wq.w);
            const ulonglong2 xa =
                *reinterpret_cast<const ulonglong2*>(&x2f[buf][i][8 * h]);
            const ulonglong2 xc =
                *reinterpret_cast<const ulonglong2*>(&x2f[buf][i][8 * h + 4]);
            u2[0][0] = fma2(wc0, xa.x, u2[0][0]);
            u2[0][1] = fma2(wc0, xa.y, u2[0][1]);
            u2[0][2] = fma2(wc0, xc.x, u2[0][2]);
            u2[0][3] = fma2(wc0, xc.y, u2[0][3]);
            u2[1][0] = fma2(wc1, xa.x, u2[1][0]);
            u2[1][1] = fma2(wc1, xa.y, u2[1][1]);
            u2[1][2] = fma2(wc1, xc.x, u2[1][2]);
            u2[1][3] = fma2(wc1, xc.y, u2[1][3]);
            u2[2][0] = fma2(wc2, xa.x, u2[2][0]);
            u2[2][1] = fma2(wc2, xa.y, u2[2][1]);
            u2[2][2] = fma2(wc2, xc.x, u2[2][2]);
            u2[2][3] = fma2(wc2, xc.y, u2[2][3]);
            u2[3][0] = fma2(wc3, xa.x, u2[3][0]);
            u2[3][1] = fma2(wc3, xa.y, u2[3][1]);
            u2[3][2] = fma2(wc3, xc.x, u2[3][2]);
            u2[3][3] = fma2(wc3, xc.y, u2[3][3]);
        }

        if (ROUND == 0) {
            #pragma unroll
            for (int c = 0; c < 4; ++c)
                #pragma unroll
                for (int k = 0; k < 4; ++k) s2[c][k] = add2(s2[c][k], u2[c][k]);
            *reinterpret_cast<float4*>(&W1s[nbuf][wiA][wcA])      = w4a;
            *reinterpret_cast<float4*>(&W1s[nbuf][wiA][wcA + 80]) = w4b;
            if (t < 64) {
                x2f[nbuf][xh * 4 + 0][xb] = xv.x;
                x2f[nbuf][xh * 4 + 1][xb] = xv.y;
                x2f[nbuf][xh * 4 + 2][xb] = xv.z;
                x2f[nbuf][xh * 4 + 3][xb] = xv.w;
            }
            __syncthreads();
        } else {
            const int eb = buf;

            // ---- agreement: dot with vsum over thread's 4 c, then
            //      4-lane shfl butterfly over jq -> full j-sum ----
            u64 agr[4];
            #pragma unroll
            for (int k = 0; k < 4; ++k) {
                const ulonglong2 va =
                    *reinterpret_cast<const ulonglong2*>(&vs_s[4 * h + k][pb]);
                const ulonglong2 vb =
                    *reinterpret_cast<const ulonglong2*>(&vs_s[4 * h + k][pb + 2]);
                u64 ag = mul2(u2[0][k], va.x);
                ag = fma2(u2[1][k], va.y, ag);
                ag = fma2(u2[2][k], vb.x, ag);
                ag = fma2(u2[3][k], vb.y, ag);
                agr[k] = ag;
            }
            #pragma unroll
            for (int k = 0; k < 4; ++k) {
                agr[k] = add2(agr[k], shfl_xor64(agr[k], 1));
                agr[k] = add2(agr[k], shfl_xor64(agr[k], 2));
            }
            // lane jq exports batch-pair k = jq
            {
                u64 mine = (jq == 0) ? agr[0] : (jq == 1) ? agr[1]
                          : (jq == 2) ? agr[2] : agr[3];
                float alo, ahi;
                upk2(mine, alo, ahi);
                // |a| tiny -> plain exp == max-shifted softmax numerically
                *reinterpret_cast<u64*>(&e_s[eb][o][8 * h + 2 * jq]) =
                    pk2(__expf(alo), __expf(ahi));
            }
            __syncthreads();

            // ---- r_s by warp 0; everyone stages n+1 under it ----
            if (t < BT) {
                float ssum = 0.f;
                #pragma unroll
                for (int oo = 0; oo < NOUT; ++oo) ssum += e_s[eb][oo][t];
                r_s[eb][t] = 1.0f / ssum;
            }
            *reinterpret_cast<float4*>(&W1s[nbuf][wiA][wcA])      = w4a;
            *reinterpret_cast<float4*>(&W1s[nbuf][wiA][wcA + 80]) = w4b;
            if (t < 64) {
                x2f[nbuf][xh * 4 + 0][xb] = xv.x;
                x2f[nbuf][xh * 4 + 1][xb] = xv.y;
                x2f[nbuf][xh * 4 + 2][xb] = xv.z;
                x2f[nbuf][xh * 4 + 3][xb] = xv.w;
            }
            __syncthreads();

            // ---- reweight: c = e * (1/sum), same c for all 4 oj ----
            #pragma unroll
            for (int k = 0; k < 4; ++k) {
                const u64 rv =
                    *reinterpret_cast<const u64*>(&r_s[eb][8 * h + 2 * k]);
                const u64 ev =
                    *reinterpret_cast<const u64*>(&e_s[eb][o][8 * h + 2 * k]);
                const u64 c2 = mul2(ev, rv);
                s2[0][k] = fma2(c2, u2[0][k], s2[0][k]);
                s2[1][k] = fma2(c2, u2[1][k], s2[1][k]);
                s2[2][k] = fma2(c2, u2[2][k], s2[2][k]);
                s2[3][k] = fma2(c2, u2[3][k], s2[3][k]);
            }
            // e_s/r_s double-buffered: next write to this buffer is 2 iters
            // away, separated by the next iteration's barriers (no WAR).
        }
    }

    // ---- write per-chunk partial, pair-major, coalesced ----
    const u64 sc = pk2((ROUND == 0) ? 0.1f : 1.0f, (ROUND == 0) ? 0.1f : 1.0f);
    #pragma unroll
    for (int k = 0; k < 4; ++k) {
        ulonglong2* dst0 = reinterpret_cast<ulonglong2*>(
            &g_partial2[nc][bp0 + 4 * h + k][pb]);
        dst0[0] = make_ulonglong2(mul2(s2[0][k], sc), mul2(s2[1][k], sc));
        dst0[1] = make_ulonglong2(mul2(s2[2][k], sc), mul2(s2[3][k], sc));
    }
}

// ------------------------------------------------------------------
// Squash: thread owns (bp, p) = one u64 pair. 48 independent LDG.64
// (MLP=48), packed add2 accumulate, dual 16-lane shfl norm,
// maintains vsum (pair-major) / emits final floats.
// 80 blocks x 256 threads = 20480.
// ------------------------------------------------------------------
template<int ROUND>
__global__ void __launch_bounds__(256)
squash_kernel(float* __restrict__ out)
{
    const int g  = blockIdx.x * 256 + threadIdx.x;   // [0, 20480)
    const int bp = g / OJ;
    const int p  = g - bp * OJ;
    const u64* gp = &g_partial2[0][0][0];

    u64 s = 0ULL;
    #pragma unroll
    for (int c = 0; c < NCH; ++c)
        s = add2(s, gp[(size_t)c * (B / 2 * OJ) + g]);

    // 16-lane groups share (bp, o): g % 16 == p % 16 == j
    u64 nsq2 = mul2(s, s);
    #pragma unroll
    for (int m = 1; m < 16; m <<= 1)
        nsq2 = add2(nsq2, shfl_xor64(nsq2, m));

    float slo, shi, nlo, nhi;
    upk2(s, slo, shi);
    upk2(nsq2, nlo, nhi);
    const float vlo = slo * (nlo / ((1.0f + nlo) * sqrtf(nlo + 1e-9f)));
    const float vhi = shi * (nhi / ((1.0f + nhi) * sqrtf(nhi + 1e-9f)));

    if (ROUND == 0)      g_vsum2[bp][p] = pk2(vlo, vhi);
    else if (ROUND == 1) g_vsum2[bp][p] = add2(g_vsum2[bp][p], pk2(vlo, vhi));
    else {
        out[(size_t)(2 * bp) * OJ + p]     = vlo;
        out[(size_t)(2 * bp + 1) * OJ + p] = vhi;
    }
}

// ------------------------------------------------------------------
// no-op launch: keeps the ncu -s/-c capture window on a round>0 pass
// ------------------------------------------------------------------
__global__ void noop_kernel() {}

// ------------------------------------------------------------------
extern "C" void kernel_launch(void* const* d_in, const int* in_sizes, int n_in,
                              void* d_out, int out_size)
{
    const float* a0 = (const float*)d_in[0];
    const float* a1 = (const float*)d_in[1];
    const float* x;
    const float* W;
    if (in_sizes[0] == B * NIN * DIN) { x = a0; W = a1; }
    else                              { x = a1; W = a0; }
    float* out = (float*)d_out;

    dim3 pg(NCH, B / BT);   // 48 x 8 = 384 CTAs

    noop_kernel<<<1, 32>>>();
    pass_kernel<0><<<pg, NT>>>(x, W);
    squash_kernel<0><<<80, 256>>>(out);
    pass_kernel<1><<<pg, NT>>>(x, W);
    squash_kernel<1><<<80, 256>>>(out);
    pass_kernel<2><<<pg, NT>>>(x, W);
    squash_kernel<2><<<80, 256>>>(out);
}